// round 2
// baseline (speedup 1.0000x reference)
#include <cuda_runtime.h>
#include <cstdint>
#include <cstddef>

#define RR 8
#define NN 300000
#define DD 128
#define AA 64
#define TILE_M 128
#define HSTRIDE 132   // 128 + 4 pad -> conflict-free A-fragment LDS
#define WSTRIDE 72    // 64 + 8 pad  -> conflict-free B-fragment LDS

__device__ __forceinline__ unsigned f2tf32(float x) {
    unsigned r;
    asm("cvt.rna.tf32.f32 %0, %1;" : "=r"(r) : "f"(x));
    return r;
}

__device__ __forceinline__ float fast_sigmoid(float x) {
    float e;
    asm("ex2.approx.f32 %0, %1;" : "=f"(e) : "f"(-1.4426950408889634f * x));
    float r;
    asm("rcp.approx.f32 %0, %1;" : "=f"(r) : "f"(1.0f + e));
    return r;
}

__device__ __forceinline__ void mma_tf32_16n8k8(float c[4],
                                                const unsigned a[4],
                                                unsigned b0, unsigned b1) {
    asm volatile(
        "mma.sync.aligned.m16n8k8.row.col.f32.tf32.tf32.f32 "
        "{%0,%1,%2,%3}, {%4,%5,%6,%7}, {%8,%9}, {%0,%1,%2,%3};"
        : "+f"(c[0]), "+f"(c[1]), "+f"(c[2]), "+f"(c[3])
        : "r"(a[0]), "r"(a[1]), "r"(a[2]), "r"(a[3]), "r"(b0), "r"(b1));
}

__device__ __forceinline__ void cp_async16(float* dst, const float* src, bool pred) {
    unsigned d = (unsigned)__cvta_generic_to_shared(dst);
    int sz = pred ? 16 : 0;
    asm volatile("cp.async.cg.shared.global [%0], [%1], 16, %2;"
                 :: "r"(d), "l"(src), "r"(sz));
}
#define CP_COMMIT() asm volatile("cp.async.commit_group;")
#define CP_WAIT(n)  asm volatile("cp.async.wait_group %0;" :: "n"(n))

// Fused: per 128-node tile: scores for all 8 relations (tf32 MMA) ->
// softmax over relations -> weighted sum (re-reads h from L2).
__global__ void __launch_bounds__(256, 1)
fused_kernel(const float* __restrict__ h,
             const float* __restrict__ w1,
             const float* __restrict__ w2,
             float* __restrict__ out) {
    extern __shared__ float smem[];
    float* sh_h   = smem;                            // 2 * 128 * 132
    float* sh_w1  = sh_h + 2 * TILE_M * HSTRIDE;     // 2 * 128 * 72
    float* sh_w2  = sh_w1 + 2 * DD * WSTRIDE;        // 512
    float* sh_sc  = sh_w2 + RR * AA;                 // 8 * 128
    float* sh_prt = sh_sc + RR * TILE_M;             // 2 * 128

    const int tid = threadIdx.x;
    const long node0 = (long)blockIdx.x * TILE_M;

    // stage all w2 (8 relations x 64) once
    sh_w2[tid] = w2[tid];
    sh_w2[tid + 256] = w2[tid + 256];

    // ---- async stage of one relation's h tile + W1 into buffer `buf` ----
    auto stage = [&](int r, int buf) {
        const float* hg = h + (size_t)r * NN * DD;
        float* hb = sh_h + buf * TILE_M * HSTRIDE;
        #pragma unroll
        for (int i = 0; i < 16; i++) {
            int idx = tid + i * 256;
            int row = idx >> 5, c4 = idx & 31;
            long node = node0 + row;
            bool p = node < NN;
            const float* src = hg + (size_t)(p ? node : 0) * DD + c4 * 4;
            cp_async16(hb + row * HSTRIDE + c4 * 4, src, p);
        }
        const float* wg = w1 + (size_t)r * DD * AA;
        float* wb = sh_w1 + buf * DD * WSTRIDE;
        #pragma unroll
        for (int i = 0; i < 8; i++) {
            int idx = tid + i * 256;
            int row = idx >> 4, c4 = idx & 15;
            cp_async16(wb + row * WSTRIDE + c4 * 4, wg + idx * 4, true);
        }
        CP_COMMIT();
    };

    stage(0, 0);

    const int w = tid >> 5, lane = tid & 31;
    const int g = lane >> 2, tg = lane & 3;
    const int m0 = (w & 3) * 32;
    const int nh = w >> 2;   // n-half

    for (int r = 0; r < RR; r++) {
        if (r + 1 < RR) { stage(r + 1, (r + 1) & 1); CP_WAIT(1); }
        else            { CP_WAIT(0); }
        __syncthreads();

        const float* hb = sh_h + (r & 1) * TILE_M * HSTRIDE;
        const float* wb = sh_w1 + (r & 1) * DD * WSTRIDE;

        float acc[2][4][4];
        #pragma unroll
        for (int mt = 0; mt < 2; mt++)
            #pragma unroll
            for (int n = 0; n < 4; n++)
                #pragma unroll
                for (int q = 0; q < 4; q++) acc[mt][n][q] = 0.f;

        for (int kc = 0; kc < 4; kc++) {          // K chunks of 32
            unsigned a[2][4][4];
            #pragma unroll
            for (int mt = 0; mt < 2; mt++)
                #pragma unroll
                for (int kt = 0; kt < 4; kt++) {
                    int row = m0 + mt * 16 + g;
                    int col = kc * 32 + kt * 8 + tg;
                    a[mt][kt][0] = f2tf32(hb[row * HSTRIDE + col]);
                    a[mt][kt][1] = f2tf32(hb[(row + 8) * HSTRIDE + col]);
                    a[mt][kt][2] = f2tf32(hb[row * HSTRIDE + col + 4]);
                    a[mt][kt][3] = f2tf32(hb[(row + 8) * HSTRIDE + col + 4]);
                }
            #pragma unroll
            for (int n = 0; n < 4; n++)
                #pragma unroll
                for (int kt = 0; kt < 4; kt++) {
                    int k = kc * 32 + kt * 8;
                    int nb = nh * 32 + n * 8;
                    unsigned b0 = f2tf32(wb[(k + tg) * WSTRIDE + nb + g]);
                    unsigned b1 = f2tf32(wb[(k + tg + 4) * WSTRIDE + nb + g]);
                    #pragma unroll
                    for (int mt = 0; mt < 2; mt++)
                        mma_tf32_16n8k8(acc[mt][n], a[mt][kt], b0, b1);
                }
        }

        // epilogue: sigmoid, dot with w2, reduce to per-node partial score
        float slo[2] = {0.f, 0.f}, shi[2] = {0.f, 0.f};
        #pragma unroll
        for (int mt = 0; mt < 2; mt++)
            #pragma unroll
            for (int n = 0; n < 4; n++) {
                int cb = nh * 32 + n * 8 + 2 * tg;
                float wa = sh_w2[r * AA + cb], wb2 = sh_w2[r * AA + cb + 1];
                slo[mt] += fast_sigmoid(acc[mt][n][0]) * wa + fast_sigmoid(acc[mt][n][1]) * wb2;
                shi[mt] += fast_sigmoid(acc[mt][n][2]) * wa + fast_sigmoid(acc[mt][n][3]) * wb2;
            }
        #pragma unroll
        for (int o = 1; o < 4; o <<= 1) {
            slo[0] += __shfl_xor_sync(0xffffffffu, slo[0], o);
            slo[1] += __shfl_xor_sync(0xffffffffu, slo[1], o);
            shi[0] += __shfl_xor_sync(0xffffffffu, shi[0], o);
            shi[1] += __shfl_xor_sync(0xffffffffu, shi[1], o);
        }
        if (tg == 0) {
            #pragma unroll
            for (int mt = 0; mt < 2; mt++) {
                sh_prt[nh * TILE_M + m0 + mt * 16 + g]     = slo[mt];
                sh_prt[nh * TILE_M + m0 + mt * 16 + g + 8] = shi[mt];
            }
        }
        __syncthreads();
        if (tid < TILE_M)
            sh_sc[r * TILE_M + tid] = sh_prt[tid] + sh_prt[TILE_M + tid];
        // next iteration's top __syncthreads protects sh_prt reuse
    }
    __syncthreads();

    // ---- softmax over relations, in place in sh_sc ----
    if (tid < TILE_M) {
        float s[RR], m = -1e30f;
        #pragma unroll
        for (int r = 0; r < RR; r++) { s[r] = sh_sc[r * TILE_M + tid]; m = fmaxf(m, s[r]); }
        float sum = 0.f;
        #pragma unroll
        for (int r = 0; r < RR; r++) { s[r] = __expf(s[r] - m); sum += s[r]; }
        float inv = 1.f / sum;
        #pragma unroll
        for (int r = 0; r < RR; r++) sh_sc[r * TILE_M + tid] = s[r] * inv;
    }
    __syncthreads();

    // ---- weighted sum: re-read h (hot in L2), accumulate in registers ----
    const float4* hp = (const float4*)h;
    float4* op = (float4*)out;
    #pragma unroll
    for (int i = 0; i < 16; i++) {
        int idx = tid + i * 256;
        int nrow = idx >> 5, c4 = idx & 31;
        long node = node0 + nrow;
        if (node >= NN) continue;
        float4 acc4 = make_float4(0.f, 0.f, 0.f, 0.f);
        #pragma unroll
        for (int r = 0; r < RR; r++) {
            float a = sh_sc[r * TILE_M + nrow];
            float4 v = hp[((size_t)r * NN + node) * 32 + c4];
            acc4.x += a * v.x; acc4.y += a * v.y;
            acc4.z += a * v.z; acc4.w += a * v.w;
        }
        op[(size_t)node * 32 + c4] = acc4;
    }
}

extern "C" void kernel_launch(void* const* d_in, const int* in_sizes, int n_in,
                              void* d_out, int out_size) {
    const float* h  = (const float*)d_in[0];
    const float* w1 = (const float*)d_in[1];
    const float* w2 = (const float*)d_in[2];
    float* out = (float*)d_out;

    const int smem_bytes =
        (2 * TILE_M * HSTRIDE + 2 * DD * WSTRIDE + RR * AA + RR * TILE_M + 2 * TILE_M) * 4;
    cudaFuncSetAttribute(fused_kernel,
                         cudaFuncAttributeMaxDynamicSharedMemorySize, smem_bytes);

    dim3 grid((NN + TILE_M - 1) / TILE_M);
    fused_kernel<<<grid, 256, smem_bytes>>>(h, w1, w2, out);
}

// round 3
// speedup vs baseline: 1.6405x; 1.6405x over previous
#include <cuda_runtime.h>
#include <cstdint>
#include <cstddef>

#define RR 8
#define NN 300000
#define DD 128
#define AA 64
#define TILE_M 128
#define HCH 36                 // h chunk row stride (32+4): banks 4g+tg distinct
#define WCH 72                 // w1 chunk row stride (64+8): banks 8tg+g distinct
#define H_BUF (TILE_M * HCH)   // 4608 floats
#define W_BUF (32 * WCH)       // 2304 floats
#define NSTEP (RR * 4)         // 8 relations x 4 k-chunks

__device__ __forceinline__ float fast_sigmoid(float x) {
    float e;
    asm("ex2.approx.f32 %0, %1;" : "=f"(e) : "f"(-1.4426950408889634f * x));
    float r;
    asm("rcp.approx.f32 %0, %1;" : "=f"(r) : "f"(1.0f + e));
    return r;
}

__device__ __forceinline__ void mma_tf32_16n8k8(float c[4],
                                                const unsigned a[4],
                                                unsigned b0, unsigned b1) {
    asm volatile(
        "mma.sync.aligned.m16n8k8.row.col.f32.tf32.tf32.f32 "
        "{%0,%1,%2,%3}, {%4,%5,%6,%7}, {%8,%9}, {%0,%1,%2,%3};"
        : "+f"(c[0]), "+f"(c[1]), "+f"(c[2]), "+f"(c[3])
        : "r"(a[0]), "r"(a[1]), "r"(a[2]), "r"(a[3]), "r"(b0), "r"(b1));
}

__device__ __forceinline__ void cp_async16(float* dst, const float* src, bool pred) {
    unsigned d = (unsigned)__cvta_generic_to_shared(dst);
    int sz = pred ? 16 : 0;
    asm volatile("cp.async.cg.shared.global [%0], [%1], 16, %2;"
                 :: "r"(d), "l"(src), "r"(sz));
}
#define CP_COMMIT() asm volatile("cp.async.commit_group;")
#define CP_WAIT(n)  asm volatile("cp.async.wait_group %0;" :: "n"(n))

__global__ void __launch_bounds__(256, 2)
fused_kernel(const float* __restrict__ h,
             const float* __restrict__ w1,
             const float* __restrict__ w2,
             float* __restrict__ out) {
    extern __shared__ float smem[];
    float* sh_h   = smem;                       // 2 * H_BUF
    float* sh_w1  = sh_h + 2 * H_BUF;           // 2 * W_BUF
    float* sh_w2  = sh_w1 + 2 * W_BUF;          // RR * AA = 512
    float* sh_sc  = sh_w2 + RR * AA;            // RR * TILE_M = 1024
    float* sh_prt = sh_sc + RR * TILE_M;        // 2 * TILE_M

    const int tid = threadIdx.x;
    const long node0 = (long)blockIdx.x * TILE_M;

    // stage all w2 once
    sh_w2[tid] = w2[tid];
    sh_w2[tid + 256] = w2[tid + 256];

    // stage one (relation, k-chunk) pair into buffer step&1
    auto stage = [&](int step) {
        int r = step >> 2, kc = step & 3, buf = step & 1;
        const float* hg = h + (size_t)r * NN * DD + kc * 32;
        float* hb = sh_h + buf * H_BUF;
        #pragma unroll
        for (int i = 0; i < 4; i++) {
            int idx = tid + i * 256;             // 0..1023
            int row = idx >> 3, c4 = idx & 7;
            long node = node0 + row;
            bool p = node < NN;
            cp_async16(hb + row * HCH + c4 * 4,
                       hg + (size_t)(p ? node : 0) * DD + c4 * 4, p);
        }
        const float* wg = w1 + (size_t)r * DD * AA + kc * 32 * AA;
        float* wb = sh_w1 + buf * W_BUF;
        #pragma unroll
        for (int i = 0; i < 2; i++) {
            int idx = tid + i * 256;             // 0..511
            int row = idx >> 4, c4 = idx & 15;
            cp_async16(wb + row * WCH + c4 * 4, wg + row * AA + c4 * 4, true);
        }
        CP_COMMIT();
    };

    stage(0);

    const int w = tid >> 5, lane = tid & 31;
    const int g = lane >> 2, tg = lane & 3;
    const int m0 = (w & 3) * 32;   // 4-way m split
    const int nh = w >> 2;         // 2-way n split

    float acc[2][4][4];

    for (int step = 0; step < NSTEP; step++) {
        const int r = step >> 2, kc = step & 3;
        if (step + 1 < NSTEP) { stage(step + 1); CP_WAIT(1); }
        else                  { CP_WAIT(0); }
        __syncthreads();   // buffer (step&1) ready; sh_sc/prt writes visible

        if (kc == 0) {
            #pragma unroll
            for (int mt = 0; mt < 2; mt++)
                #pragma unroll
                for (int n = 0; n < 4; n++)
                    #pragma unroll
                    for (int q = 0; q < 4; q++) acc[mt][n][q] = 0.f;
        }

        const unsigned* hh = (const unsigned*)(sh_h + (step & 1) * H_BUF);
        const unsigned* ww = (const unsigned*)(sh_w1 + (step & 1) * W_BUF);

        #pragma unroll
        for (int kt = 0; kt < 4; kt++) {
            unsigned a[2][4];
            #pragma unroll
            for (int mt = 0; mt < 2; mt++) {
                int row = m0 + mt * 16 + g;
                int col = kt * 8 + tg;
                a[mt][0] = hh[row * HCH + col];
                a[mt][1] = hh[(row + 8) * HCH + col];
                a[mt][2] = hh[row * HCH + col + 4];
                a[mt][3] = hh[(row + 8) * HCH + col + 4];
            }
            #pragma unroll
            for (int n = 0; n < 4; n++) {
                int nb = nh * 32 + n * 8;
                unsigned b0 = ww[(kt * 8 + tg) * WCH + nb + g];
                unsigned b1 = ww[(kt * 8 + tg + 4) * WCH + nb + g];
                mma_tf32_16n8k8(acc[0][n], a[0], b0, b1);
                mma_tf32_16n8k8(acc[1][n], a[1], b0, b1);
            }
        }

        if (kc == 3) {
            // epilogue: sigmoid, dot with w2, reduce to per-node score
            float slo[2] = {0.f, 0.f}, shi[2] = {0.f, 0.f};
            #pragma unroll
            for (int mt = 0; mt < 2; mt++)
                #pragma unroll
                for (int n = 0; n < 4; n++) {
                    int cb = nh * 32 + n * 8 + 2 * tg;
                    float wa = sh_w2[r * AA + cb], wb2 = sh_w2[r * AA + cb + 1];
                    slo[mt] += fast_sigmoid(acc[mt][n][0]) * wa + fast_sigmoid(acc[mt][n][1]) * wb2;
                    shi[mt] += fast_sigmoid(acc[mt][n][2]) * wa + fast_sigmoid(acc[mt][n][3]) * wb2;
                }
            #pragma unroll
            for (int o = 1; o < 4; o <<= 1) {
                slo[0] += __shfl_xor_sync(0xffffffffu, slo[0], o);
                slo[1] += __shfl_xor_sync(0xffffffffu, slo[1], o);
                shi[0] += __shfl_xor_sync(0xffffffffu, shi[0], o);
                shi[1] += __shfl_xor_sync(0xffffffffu, shi[1], o);
            }
            if (tg == 0) {
                #pragma unroll
                for (int mt = 0; mt < 2; mt++) {
                    sh_prt[nh * TILE_M + m0 + mt * 16 + g]     = slo[mt];
                    sh_prt[nh * TILE_M + m0 + mt * 16 + g + 8] = shi[mt];
                }
            }
        }
        __syncthreads();   // all reads of buffer step&1 done; prt complete
        if (kc == 3 && tid < TILE_M)
            sh_sc[r * TILE_M + tid] = sh_prt[tid] + sh_prt[TILE_M + tid];
        // next top __syncthreads orders this write before any reuse
    }
    __syncthreads();

    // ---- softmax over relations, in place in sh_sc ----
    if (tid < TILE_M) {
        float s[RR], m = -1e30f;
        #pragma unroll
        for (int r = 0; r < RR; r++) { s[r] = sh_sc[r * TILE_M + tid]; m = fmaxf(m, s[r]); }
        float sum = 0.f;
        #pragma unroll
        for (int r = 0; r < RR; r++) { s[r] = __expf(s[r] - m); sum += s[r]; }
        float inv = 1.f / sum;
        #pragma unroll
        for (int r = 0; r < RR; r++) sh_sc[r * TILE_M + tid] = s[r] * inv;
    }
    __syncthreads();

    // ---- weighted sum: re-read h (hot in L2), accumulate in registers ----
    const float4* hp = (const float4*)h;
    float4* op = (float4*)out;
    #pragma unroll
    for (int i = 0; i < 16; i++) {
        int idx = tid + i * 256;
        int nrow = idx >> 5, c4 = idx & 31;
        long node = node0 + nrow;
        if (node >= NN) continue;
        float4 acc4 = make_float4(0.f, 0.f, 0.f, 0.f);
        #pragma unroll
        for (int r = 0; r < RR; r++) {
            float a = sh_sc[r * TILE_M + nrow];
            float4 v = hp[((size_t)r * NN + node) * 32 + c4];
            acc4.x += a * v.x; acc4.y += a * v.y;
            acc4.z += a * v.z; acc4.w += a * v.w;
        }
        op[(size_t)node * 32 + c4] = acc4;
    }
}

extern "C" void kernel_launch(void* const* d_in, const int* in_sizes, int n_in,
                              void* d_out, int out_size) {
    const float* h  = (const float*)d_in[0];
    const float* w1 = (const float*)d_in[1];
    const float* w2 = (const float*)d_in[2];
    float* out = (float*)d_out;

    const int smem_bytes =
        (2 * H_BUF + 2 * W_BUF + RR * AA + RR * TILE_M + 2 * TILE_M) * 4;
    cudaFuncSetAttribute(fused_kernel,
                         cudaFuncAttributeMaxDynamicSharedMemorySize, smem_bytes);

    dim3 grid((NN + TILE_M - 1) / TILE_M);
    fused_kernel<<<grid, 256, smem_bytes>>>(h, w1, w2, out);
}